// round 10
// baseline (speedup 1.0000x reference)
#include <cuda_runtime.h>
#include <cuda_fp16.h>
#include <cstdint>

#define CK     512
#define VDIM   1024
#define MTOT   131072
#define BM     128
#define BN     128
#define BK     64
#define NCHUNK (CK / BK)       // 8
#define NTHREADS 256

#define A_BYTES     16384      // 128 rows x 128B fp16
#define STAGE_BYTES 32768      // A 16KB + B 16KB
#define SMEM_DYN    (3 * STAGE_BYTES + 256)   // 96KB + pad -> 2 CTAs/SM

// fp16 scratch: tanh(enc+pred) precomputed once, W converted once.
__device__ __half Ah_g[(size_t)MTOT * CK];   // 128 MB
__device__ __half Wh_g[(size_t)VDIM * CK];   // 1 MB

__device__ __forceinline__ float fast_tanh(float x) {
    float y; asm("tanh.approx.f32 %0, %1;" : "=f"(y) : "f"(x)); return y;
}
__device__ __forceinline__ uint32_t smem_u32(const void* p) {
    uint32_t a;
    asm("{ .reg .u64 t; cvta.to.shared.u64 t, %1; cvt.u32.u64 %0, t; }" : "=r"(a) : "l"(p));
    return a;
}
__device__ __forceinline__ uint32_t swz(uint32_t x) { return x ^ ((x >> 3) & 0x70); }

#define CP16(s, g) asm volatile("cp.async.cg.shared.global [%0], [%1], 16;" :: "r"(s), "l"(g))
#define CPCOMMIT() asm volatile("cp.async.commit_group;" ::: "memory")

// ---------------- prolog kernels ----------------
__global__ void __launch_bounds__(256) conv_w(const float* __restrict__ W) {
    const int i = blockIdx.x * 256 + threadIdx.x;       // 131072 float4s
    const float4 w = reinterpret_cast<const float4*>(W)[i];
    __half2* o = reinterpret_cast<__half2*>(Wh_g);
    o[2 * i]     = __floats2half2_rn(w.x, w.y);
    o[2 * i + 1] = __floats2half2_rn(w.z, w.w);
}

__global__ void __launch_bounds__(256) conv_a(const float* __restrict__ enc,
                                              const float* __restrict__ pred) {
    const int g = blockIdx.x * 256 + threadIdx.x;       // float4 id
    const int m = g >> 7;
    const int t = g & 127;
    const float4 e = reinterpret_cast<const float4*>(enc  + (size_t)(m >> 6) * CK)[t];
    const float4 p = reinterpret_cast<const float4*>(pred + (size_t)(((m >> 14) << 6) | (m & 63)) * CK)[t];
    __half2 h0 = __floats2half2_rn(fast_tanh(e.x + p.x), fast_tanh(e.y + p.y));
    __half2 h1 = __floats2half2_rn(fast_tanh(e.z + p.z), fast_tanh(e.w + p.w));
    __half2* o = reinterpret_cast<__half2*>(Ah_g);
    o[2 * (size_t)g]     = h0;
    o[2 * (size_t)g + 1] = h1;
}

// ---------------- main GEMM: 128x128 tile, 8 warps, 2 CTAs/SM ----------------
__global__ void __launch_bounds__(NTHREADS, 2)
joiner_gemm(const float* __restrict__ bias, float* __restrict__ out)
{
    extern __shared__ char smem_raw[];
    const uint32_t smemBase = (smem_u32(smem_raw) + 127u) & ~127u;

    const int tid  = threadIdx.x;
    const int lane = tid & 31;
    const int wid  = tid >> 5;
    const int n0 = blockIdx.x * BN;       // x = n-tile (8) -> A L2 reuse within wave
    const int m0 = blockIdx.y * BM;       // y = m-tile (1024)
    const int warpM = (wid & 1) * 64;     // 2 warp-rows of 64
    const int warpN = (wid >> 1) * 32;    // 4 warp-cols of 32

    float acc[4][4][4];
    #pragma unroll
    for (int mt = 0; mt < 4; ++mt)
        #pragma unroll
        for (int nt = 0; nt < 4; ++nt)
            #pragma unroll
            for (int i = 0; i < 4; ++i) acc[mt][nt][i] = 0.0f;

    const __half* gA0 = Ah_g + (size_t)m0 * CK;
    const __half* gB0 = Wh_g + (size_t)n0 * CK;

    // ---- cp.async stage issue: A 4x16B + B 4x16B per thread ----
    auto issue_stage = [&](int c, int s) {
        const uint32_t sa = smemBase + (uint32_t)s * STAGE_BYTES;
        const uint32_t sb = sa + A_BYTES;
        const __half* gA = gA0 + c * BK;
        const __half* gB = gB0 + c * BK;
        #pragma unroll
        for (int i = 0; i < 4; ++i) {
            const int q = tid + i * 256;
            const int row = q >> 3, c16 = q & 7;
            CP16(sa + swz((uint32_t)(row * 128 + c16 * 16)), gA + (size_t)row * CK + c16 * 8);
        }
        #pragma unroll
        for (int i = 0; i < 4; ++i) {
            const int q = tid + i * 256;
            const int row = q >> 3, c16 = q & 7;
            CP16(sb + swz((uint32_t)(row * 128 + c16 * 16)), gB + (size_t)row * CK + c16 * 8);
        }
        CPCOMMIT();
    };

    auto compute_stage = [&](int s) {
        const uint32_t sa = smemBase + (uint32_t)s * STAGE_BYTES;
        const uint32_t sb = sa + A_BYTES;
        // A: lanes 0-15 -> 16 rows, k-half 0; lanes 16-31 -> k-half 1
        const uint32_t kbAoff = (uint32_t)((lane >> 4) << 4);
        // B (non-trans): lane group j=lane/8 -> matrix j = (n-block j/2, k-half j&1)
        const int jgrp = lane >> 3;
        const uint32_t bNoff = (uint32_t)((jgrp >> 1) * 8 + (lane & 7));
        const uint32_t bKoff = (uint32_t)((jgrp & 1) * 16);

        uint32_t a[2][4][4];                      // double-buffered A fragments
        auto loadA = [&](int k16, uint32_t (&af)[4][4]) {
            const uint32_t kbA = (uint32_t)(k16 * 32) + kbAoff;
            #pragma unroll
            for (int mt = 0; mt < 4; ++mt) {
                const uint32_t ad = sa + swz((uint32_t)((warpM + mt * 16 + (lane & 15)) * 128) + kbA);
                asm volatile("ldmatrix.sync.aligned.m8n8.x4.shared.b16 {%0,%1,%2,%3}, [%4];"
                    : "=r"(af[mt][0]), "=r"(af[mt][1]), "=r"(af[mt][2]), "=r"(af[mt][3]) : "r"(ad));
            }
        };

        loadA(0, a[0]);
        #pragma unroll
        for (int k16 = 0; k16 < 4; ++k16) {
            if (k16 < 3) loadA(k16 + 1, a[(k16 + 1) & 1]);   // prefetch next A under this k16's MMAs
            uint32_t b[4][2];
            const uint32_t kbB = (uint32_t)(k16 * 32) + bKoff;
            #pragma unroll
            for (int np = 0; np < 2; ++np) {
                const uint32_t ad = sb + swz((uint32_t)(warpN + np * 16 + bNoff) * 128u + kbB);
                asm volatile("ldmatrix.sync.aligned.m8n8.x4.shared.b16 {%0,%1,%2,%3}, [%4];"
                    : "=r"(b[2 * np][0]), "=r"(b[2 * np][1]), "=r"(b[2 * np + 1][0]), "=r"(b[2 * np + 1][1])
                    : "r"(ad));
            }
            #pragma unroll
            for (int mt = 0; mt < 4; ++mt)
                #pragma unroll
                for (int nt = 0; nt < 4; ++nt)
                    asm volatile(
                        "mma.sync.aligned.m16n8k16.row.col.f32.f16.f16.f32 "
                        "{%0,%1,%2,%3},{%4,%5,%6,%7},{%8,%9},{%0,%1,%2,%3};"
                        : "+f"(acc[mt][nt][0]), "+f"(acc[mt][nt][1]),
                          "+f"(acc[mt][nt][2]), "+f"(acc[mt][nt][3])
                        : "r"(a[k16 & 1][mt][0]), "r"(a[k16 & 1][mt][1]),
                          "r"(a[k16 & 1][mt][2]), "r"(a[k16 & 1][mt][3]),
                          "r"(b[nt][0]), "r"(b[nt][1]));
        }
    };

    issue_stage(0, 0);
    issue_stage(1, 1);

    #pragma unroll 1
    for (int c = 0; c < NCHUNK; ++c) {
        if (c < NCHUNK - 1) asm volatile("cp.async.wait_group 1;" ::: "memory");
        else                asm volatile("cp.async.wait_group 0;" ::: "memory");
        __syncthreads();
        if (c + 2 < NCHUNK) issue_stage(c + 2, (c + 2) % 3);   // in flight under compute
        compute_stage(c % 3);
    }

    // ---- epilogue: bias + fp32 store ----
    const int gr = lane >> 2;
    const int gc = (lane & 3) * 2;
    #pragma unroll
    for (int mt = 0; mt < 4; ++mt) {
        const int m = m0 + warpM + mt * 16 + gr;
        #pragma unroll
        for (int nt = 0; nt < 4; ++nt) {
            const int n = n0 + warpN + nt * 8 + gc;
            const float2 bb = *reinterpret_cast<const float2*>(bias + n);
            float2 v0, v1;
            v0.x = acc[mt][nt][0] + bb.x; v0.y = acc[mt][nt][1] + bb.y;
            v1.x = acc[mt][nt][2] + bb.x; v1.y = acc[mt][nt][3] + bb.y;
            *reinterpret_cast<float2*>(out + (size_t)m * VDIM + n)       = v0;
            *reinterpret_cast<float2*>(out + (size_t)(m + 8) * VDIM + n) = v1;
        }
    }
}

extern "C" void kernel_launch(void* const* d_in, const int* in_sizes, int n_in,
                              void* d_out, int out_size) {
    const float* enc  = (const float*)d_in[0];   // (8,256,512)
    const float* pred = (const float*)d_in[1];   // (8,64,512)
    const float* W    = (const float*)d_in[2];   // (1024,512)
    const float* b    = (const float*)d_in[3];   // (1024,)
    float* out = (float*)d_out;                  // (8,256,64,1024) fp32

    cudaFuncSetAttribute(joiner_gemm, cudaFuncAttributeMaxDynamicSharedMemorySize, SMEM_DYN);

    conv_w<<<VDIM * CK / 4 / 256, 256>>>(W);                   // 512 blocks
    conv_a<<<(size_t)MTOT * CK / 4 / 256, 256>>>(enc, pred);   // 65536 blocks
    dim3 grid(VDIM / BN, MTOT / BM);                           // (8, 1024)
    joiner_gemm<<<grid, NTHREADS, SMEM_DYN>>>(b, out);
}

// round 11
// speedup vs baseline: 1.0303x; 1.0303x over previous
#include <cuda_runtime.h>
#include <cuda_fp16.h>
#include <cstdint>

#define CK     512
#define VDIM   1024
#define MTOT   131072
#define BM     128
#define BN     128
#define BK     64
#define NCHUNK (CK / BK)       // 8
#define NTHREADS 128

#define A_BYTES     16384      // 128 rows x 128B fp16
#define STAGE_BYTES 32768      // A 16KB + B 16KB
#define SMEM_DYN    (3 * STAGE_BYTES + 256)   // 96KB -> 2 CTAs/SM

// fp16 scratch: tanh(enc+pred) precomputed once, W converted once.
__device__ __half Ah_g[(size_t)MTOT * CK];   // 128 MB
__device__ __half Wh_g[(size_t)VDIM * CK];   // 1 MB

__device__ __forceinline__ float fast_tanh(float x) {
    float y; asm("tanh.approx.f32 %0, %1;" : "=f"(y) : "f"(x)); return y;
}
__device__ __forceinline__ uint32_t smem_u32(const void* p) {
    uint32_t a;
    asm("{ .reg .u64 t; cvta.to.shared.u64 t, %1; cvt.u32.u64 %0, t; }" : "=r"(a) : "l"(p));
    return a;
}
__device__ __forceinline__ uint32_t swz(uint32_t x) { return x ^ ((x >> 3) & 0x70); }

#define CP16(s, g) asm volatile("cp.async.cg.shared.global [%0], [%1], 16;" :: "r"(s), "l"(g))
#define CPCOMMIT() asm volatile("cp.async.commit_group;" ::: "memory")

// ---------------- prolog kernels ----------------
__global__ void __launch_bounds__(256) conv_w(const float* __restrict__ W) {
    const int i = blockIdx.x * 256 + threadIdx.x;       // 131072 float4s
    const float4 w = reinterpret_cast<const float4*>(W)[i];
    __half2* o = reinterpret_cast<__half2*>(Wh_g);
    o[2 * i]     = __floats2half2_rn(w.x, w.y);
    o[2 * i + 1] = __floats2half2_rn(w.z, w.w);
}

__global__ void __launch_bounds__(256) conv_a(const float* __restrict__ enc,
                                              const float* __restrict__ pred) {
    const int g = blockIdx.x * 256 + threadIdx.x;       // float4 id
    const int m = g >> 7;
    const int t = g & 127;
    const float4 e = reinterpret_cast<const float4*>(enc  + (size_t)(m >> 6) * CK)[t];
    const float4 p = reinterpret_cast<const float4*>(pred + (size_t)(((m >> 14) << 6) | (m & 63)) * CK)[t];
    __half2 h0 = __floats2half2_rn(fast_tanh(e.x + p.x), fast_tanh(e.y + p.y));
    __half2 h1 = __floats2half2_rn(fast_tanh(e.z + p.z), fast_tanh(e.w + p.w));
    __half2* o = reinterpret_cast<__half2*>(Ah_g);
    o[2 * (size_t)g]     = h0;
    o[2 * (size_t)g + 1] = h1;
}

// ------- main GEMM: 128x128 tile, 4 warps (64x64 each), 2 CTAs/SM -------
__global__ void __launch_bounds__(NTHREADS, 2)
joiner_gemm(const float* __restrict__ bias, float* __restrict__ out)
{
    extern __shared__ char smem_raw[];
    const uint32_t smemBase = (smem_u32(smem_raw) + 127u) & ~127u;

    const int tid  = threadIdx.x;
    const int lane = tid & 31;
    const int wid  = tid >> 5;
    const int n0 = blockIdx.x * BN;       // x = n-tile (8) -> A L2 reuse within wave
    const int m0 = blockIdx.y * BM;       // y = m-tile (1024)
    const int warpM = (wid & 1) * 64;     // 2 warp-rows of 64
    const int warpN = (wid >> 1) * 64;    // 2 warp-cols of 64

    float acc[4][8][4];
    #pragma unroll
    for (int mt = 0; mt < 4; ++mt)
        #pragma unroll
        for (int nt = 0; nt < 8; ++nt)
            #pragma unroll
            for (int i = 0; i < 4; ++i) acc[mt][nt][i] = 0.0f;

    const __half* gA0 = Ah_g + (size_t)m0 * CK;
    const __half* gB0 = Wh_g + (size_t)n0 * CK;

    // ---- cp.async stage issue: A 8x16B + B 8x16B per thread (128 thr) ----
    auto issue_stage = [&](int c, int s) {
        const uint32_t sa = smemBase + (uint32_t)s * STAGE_BYTES;
        const uint32_t sb = sa + A_BYTES;
        const __half* gA = gA0 + c * BK;
        const __half* gB = gB0 + c * BK;
        #pragma unroll
        for (int i = 0; i < 8; ++i) {
            const int q = tid + i * 128;
            const int row = q >> 3, c16 = q & 7;
            CP16(sa + swz((uint32_t)(row * 128 + c16 * 16)), gA + (size_t)row * CK + c16 * 8);
        }
        #pragma unroll
        for (int i = 0; i < 8; ++i) {
            const int q = tid + i * 128;
            const int row = q >> 3, c16 = q & 7;
            CP16(sb + swz((uint32_t)(row * 128 + c16 * 16)), gB + (size_t)row * CK + c16 * 8);
        }
        CPCOMMIT();
    };

    auto compute_stage = [&](int s) {
        const uint32_t sa = smemBase + (uint32_t)s * STAGE_BYTES;
        const uint32_t sb = sa + A_BYTES;
        // A: lanes 0-15 -> 16 rows, k-half 0; lanes 16-31 -> k-half 1
        const uint32_t kbAoff = (uint32_t)((lane >> 4) << 4);
        // B (non-trans): lane group j=lane/8 -> matrix j = (n-block j/2, k-half j&1)
        const int jgrp = lane >> 3;
        const uint32_t bNoff = (uint32_t)((jgrp >> 1) * 8 + (lane & 7));
        const uint32_t bKoff = (uint32_t)((jgrp & 1) * 16);
        #pragma unroll
        for (int k16 = 0; k16 < 4; ++k16) {
            uint32_t a[4][4];
            const uint32_t kbA = (uint32_t)(k16 * 32) + kbAoff;
            #pragma unroll
            for (int mt = 0; mt < 4; ++mt) {
                const uint32_t ad = sa + swz((uint32_t)((warpM + mt * 16 + (lane & 15)) * 128) + kbA);
                asm volatile("ldmatrix.sync.aligned.m8n8.x4.shared.b16 {%0,%1,%2,%3}, [%4];"
                    : "=r"(a[mt][0]), "=r"(a[mt][1]), "=r"(a[mt][2]), "=r"(a[mt][3]) : "r"(ad));
            }
            uint32_t b[8][2];
            const uint32_t kbB = (uint32_t)(k16 * 32) + bKoff;
            #pragma unroll
            for (int np = 0; np < 4; ++np) {
                const uint32_t ad = sb + swz((uint32_t)(warpN + np * 16 + bNoff) * 128u + kbB);
                asm volatile("ldmatrix.sync.aligned.m8n8.x4.shared.b16 {%0,%1,%2,%3}, [%4];"
                    : "=r"(b[2 * np][0]), "=r"(b[2 * np][1]), "=r"(b[2 * np + 1][0]), "=r"(b[2 * np + 1][1])
                    : "r"(ad));
            }
            #pragma unroll
            for (int mt = 0; mt < 4; ++mt)
                #pragma unroll
                for (int nt = 0; nt < 8; ++nt)
                    asm volatile(
                        "mma.sync.aligned.m16n8k16.row.col.f32.f16.f16.f32 "
                        "{%0,%1,%2,%3},{%4,%5,%6,%7},{%8,%9},{%0,%1,%2,%3};"
                        : "+f"(acc[mt][nt][0]), "+f"(acc[mt][nt][1]),
                          "+f"(acc[mt][nt][2]), "+f"(acc[mt][nt][3])
                        : "r"(a[mt][0]), "r"(a[mt][1]), "r"(a[mt][2]), "r"(a[mt][3]),
                          "r"(b[nt][0]), "r"(b[nt][1]));
        }
    };

    issue_stage(0, 0);
    issue_stage(1, 1);

    #pragma unroll 1
    for (int c = 0; c < NCHUNK; ++c) {
        if (c < NCHUNK - 1) asm volatile("cp.async.wait_group 1;" ::: "memory");
        else                asm volatile("cp.async.wait_group 0;" ::: "memory");
        __syncthreads();
        compute_stage(c % 3);
        if (c + 2 < NCHUNK) issue_stage(c + 2, (c + 2) % 3);
    }

    // ---- epilogue: bias + fp32 store ----
    const int gr = lane >> 2;
    const int gc = (lane & 3) * 2;
    #pragma unroll
    for (int mt = 0; mt < 4; ++mt) {
        const int m = m0 + warpM + mt * 16 + gr;
        #pragma unroll
        for (int nt = 0; nt < 8; ++nt) {
            const int n = n0 + warpN + nt * 8 + gc;
            const float2 bb = *reinterpret_cast<const float2*>(bias + n);
            float2 v0, v1;
            v0.x = acc[mt][nt][0] + bb.x; v0.y = acc[mt][nt][1] + bb.y;
            v1.x = acc[mt][nt][2] + bb.x; v1.y = acc[mt][nt][3] + bb.y;
            *reinterpret_cast<float2*>(out + (size_t)m * VDIM + n)       = v0;
            *reinterpret_cast<float2*>(out + (size_t)(m + 8) * VDIM + n) = v1;
        }
    }
}

extern "C" void kernel_launch(void* const* d_in, const int* in_sizes, int n_in,
                              void* d_out, int out_size) {
    const float* enc  = (const float*)d_in[0];   // (8,256,512)
    const float* pred = (const float*)d_in[1];   // (8,64,512)
    const float* W    = (const float*)d_in[2];   // (1024,512)
    const float* b    = (const float*)d_in[3];   // (1024,)
    float* out = (float*)d_out;                  // (8,256,64,1024) fp32

    cudaFuncSetAttribute(joiner_gemm, cudaFuncAttributeMaxDynamicSharedMemorySize, SMEM_DYN);

    conv_w<<<VDIM * CK / 4 / 256, 256>>>(W);                   // 512 blocks
    conv_a<<<(size_t)MTOT * CK / 4 / 256, 256>>>(enc, pred);   // 65536 blocks
    dim3 grid(VDIM / BN, MTOT / BM);                           // (8, 1024)
    joiner_gemm<<<grid, NTHREADS, SMEM_DYN>>>(b, out);
}

// round 12
// speedup vs baseline: 1.0541x; 1.0230x over previous
#include <cuda_runtime.h>
#include <cuda.h>
#include <cuda_fp16.h>
#include <cstdint>

#define CK     512
#define VDIM   1024
#define MTOT   131072
#define BM     128
#define BN     128
#define BK     64
#define NCHUNK (CK / BK)       // 8
#define NTHREADS 128

#define A_BYTES     16384      // 128 rows x 128B fp16
#define STAGE_BYTES 32768      // A 16KB + B 16KB
#define MBAR_OFF    98304      // after 3 stages
#define SMEM_DYN    (98304 + 128 + 1024)   // stages + mbars + align slack

// fp16 scratch: tanh(enc+pred) precomputed once, W converted once.
__device__ __half Ah_g[(size_t)MTOT * CK];   // 128 MB
__device__ __half Wh_g[(size_t)VDIM * CK];   // 1 MB

__device__ __forceinline__ float fast_tanh(float x) {
    float y; asm("tanh.approx.f32 %0, %1;" : "=f"(y) : "f"(x)); return y;
}
__device__ __forceinline__ uint32_t smem_u32(const void* p) {
    uint32_t a;
    asm("{ .reg .u64 t; cvta.to.shared.u64 t, %1; cvt.u32.u64 %0, t; }" : "=r"(a) : "l"(p));
    return a;
}
__device__ __forceinline__ uint32_t swz(uint32_t x) { return x ^ ((x >> 3) & 0x70); }

__device__ __forceinline__ void mbar_wait(uint32_t mbar, uint32_t parity) {
    uint32_t done;
    asm volatile(
        "{\n\t.reg .pred p;\n\t"
        "mbarrier.try_wait.parity.acquire.cta.shared::cta.b64 p, [%1], %2;\n\t"
        "selp.b32 %0, 1, 0, p;\n\t}"
        : "=r"(done) : "r"(mbar), "r"(parity) : "memory");
    if (!done) {
        asm volatile(
            "{\n\t.reg .pred P1;\n\t"
            "W_%=:\n\t"
            "mbarrier.try_wait.parity.acquire.cta.shared::cta.b64 P1, [%0], %1, 0x989680;\n\t"
            "@P1 bra.uni D_%=;\n\t"
            "bra.uni W_%=;\n\t"
            "D_%=:\n\t}"
            :: "r"(mbar), "r"(parity) : "memory");
    }
}

// ---------------- prolog kernels ----------------
__global__ void __launch_bounds__(256) conv_w(const float* __restrict__ W) {
    const int i = blockIdx.x * 256 + threadIdx.x;       // 131072 float4s
    const float4 w = reinterpret_cast<const float4*>(W)[i];
    __half2* o = reinterpret_cast<__half2*>(Wh_g);
    o[2 * i]     = __floats2half2_rn(w.x, w.y);
    o[2 * i + 1] = __floats2half2_rn(w.z, w.w);
}

__global__ void __launch_bounds__(256) conv_a(const float* __restrict__ enc,
                                              const float* __restrict__ pred) {
    const int g = blockIdx.x * 256 + threadIdx.x;       // float4 id
    const int m = g >> 7;
    const int t = g & 127;
    const float4 e = reinterpret_cast<const float4*>(enc  + (size_t)(m >> 6) * CK)[t];
    const float4 p = reinterpret_cast<const float4*>(pred + (size_t)(((m >> 14) << 6) | (m & 63)) * CK)[t];
    __half2 h0 = __floats2half2_rn(fast_tanh(e.x + p.x), fast_tanh(e.y + p.y));
    __half2 h1 = __floats2half2_rn(fast_tanh(e.z + p.z), fast_tanh(e.w + p.w));
    __half2* o = reinterpret_cast<__half2*>(Ah_g);
    o[2 * (size_t)g]     = h0;
    o[2 * (size_t)g + 1] = h1;
}

// ------- main GEMM: 128x128 tile, 4 warps (64x64 each), 2 CTAs/SM, TMA staging -------
__global__ void __launch_bounds__(NTHREADS, 2)
joiner_gemm(const __grid_constant__ CUtensorMap tmA,
            const __grid_constant__ CUtensorMap tmB,
            const float* __restrict__ bias, float* __restrict__ out)
{
    extern __shared__ char smem_raw[];
    const uint32_t smemBase = (smem_u32(smem_raw) + 1023u) & ~1023u;   // 1024B for SW128 atoms

    const int tid  = threadIdx.x;
    const int lane = tid & 31;
    const int wid  = tid >> 5;
    const int n0 = blockIdx.x * BN;       // x = n-tile (8) -> A L2 reuse within wave
    const int m0 = blockIdx.y * BM;       // y = m-tile (1024)
    const int warpM = (wid & 1) * 64;
    const int warpN = (wid >> 1) * 64;

    const uint32_t mbar0 = smemBase + MBAR_OFF;

    if (tid == 0) {
        #pragma unroll
        for (int s = 0; s < 3; ++s)
            asm volatile("mbarrier.init.shared.b64 [%0], 1;" :: "r"(mbar0 + s * 8) : "memory");
    }
    __syncthreads();

    float acc[4][8][4];
    #pragma unroll
    for (int mt = 0; mt < 4; ++mt)
        #pragma unroll
        for (int nt = 0; nt < 8; ++nt)
            #pragma unroll
            for (int i = 0; i < 4; ++i) acc[mt][nt][i] = 0.0f;

    // ---- TMA stage issue (thread 0): A box [128B x 128 rows], B box same ----
    auto issue_stage = [&](int c, int s) {
        const uint32_t sa = smemBase + (uint32_t)s * STAGE_BYTES;
        const uint32_t sb = sa + A_BYTES;
        const uint32_t mb = mbar0 + (uint32_t)s * 8;
        asm volatile("mbarrier.arrive.expect_tx.shared.b64 _, [%0], %1;"
                     :: "r"(mb), "r"((uint32_t)STAGE_BYTES) : "memory");
        const int xb = c * (BK * 2);      // byte col within row
        asm volatile(
            "cp.async.bulk.tensor.2d.shared::cta.global.tile.mbarrier::complete_tx::bytes "
            "[%0], [%1, {%2, %3}], [%4];"
            :: "r"(sa), "l"(&tmA), "r"(xb), "r"(m0), "r"(mb) : "memory");
        asm volatile(
            "cp.async.bulk.tensor.2d.shared::cta.global.tile.mbarrier::complete_tx::bytes "
            "[%0], [%1, {%2, %3}], [%4];"
            :: "r"(sb), "l"(&tmB), "r"(xb), "r"(n0), "r"(mb) : "memory");
    };

    auto compute_stage = [&](int s) {
        const uint32_t sa = smemBase + (uint32_t)s * STAGE_BYTES;
        const uint32_t sb = sa + A_BYTES;
        const uint32_t kbAoff = (uint32_t)((lane >> 4) << 4);
        const int jgrp = lane >> 3;
        const uint32_t bNoff = (uint32_t)((jgrp >> 1) * 8 + (lane & 7));
        const uint32_t bKoff = (uint32_t)((jgrp & 1) * 16);
        #pragma unroll
        for (int k16 = 0; k16 < 4; ++k16) {
            uint32_t a[4][4];
            const uint32_t kbA = (uint32_t)(k16 * 32) + kbAoff;
            #pragma unroll
            for (int mt = 0; mt < 4; ++mt) {
                const uint32_t ad = sa + swz((uint32_t)((warpM + mt * 16 + (lane & 15)) * 128) + kbA);
                asm volatile("ldmatrix.sync.aligned.m8n8.x4.shared.b16 {%0,%1,%2,%3}, [%4];"
                    : "=r"(a[mt][0]), "=r"(a[mt][1]), "=r"(a[mt][2]), "=r"(a[mt][3]) : "r"(ad));
            }
            uint32_t b[8][2];
            const uint32_t kbB = (uint32_t)(k16 * 32) + bKoff;
            #pragma unroll
            for (int np = 0; np < 4; ++np) {
                const uint32_t ad = sb + swz((uint32_t)(warpN + np * 16 + bNoff) * 128u + kbB);
                asm volatile("ldmatrix.sync.aligned.m8n8.x4.shared.b16 {%0,%1,%2,%3}, [%4];"
                    : "=r"(b[2 * np][0]), "=r"(b[2 * np][1]), "=r"(b[2 * np + 1][0]), "=r"(b[2 * np + 1][1])
                    : "r"(ad));
            }
            #pragma unroll
            for (int mt = 0; mt < 4; ++mt)
                #pragma unroll
                for (int nt = 0; nt < 8; ++nt)
                    asm volatile(
                        "mma.sync.aligned.m16n8k16.row.col.f32.f16.f16.f32 "
                        "{%0,%1,%2,%3},{%4,%5,%6,%7},{%8,%9},{%0,%1,%2,%3};"
                        : "+f"(acc[mt][nt][0]), "+f"(acc[mt][nt][1]),
                          "+f"(acc[mt][nt][2]), "+f"(acc[mt][nt][3])
                        : "r"(a[mt][0]), "r"(a[mt][1]), "r"(a[mt][2]), "r"(a[mt][3]),
                          "r"(b[nt][0]), "r"(b[nt][1]));
        }
    };

    if (tid == 0) { issue_stage(0, 0); issue_stage(1, 1); }

    #pragma unroll 1
    for (int c = 0; c < NCHUNK; ++c) {
        mbar_wait(mbar0 + (uint32_t)(c % 3) * 8, (uint32_t)((c / 3) & 1));
        compute_stage(c % 3);
        __syncthreads();                          // all reads of this stage done
        if (tid == 0 && c + 2 < NCHUNK) issue_stage(c + 2, (c + 2) % 3);
    }

    // ---- epilogue: bias + fp32 store ----
    const int gr = lane >> 2;
    const int gc = (lane & 3) * 2;
    #pragma unroll
    for (int mt = 0; mt < 4; ++mt) {
        const int m = m0 + warpM + mt * 16 + gr;
        #pragma unroll
        for (int nt = 0; nt < 8; ++nt) {
            const int n = n0 + warpN + nt * 8 + gc;
            const float2 bb = *reinterpret_cast<const float2*>(bias + n);
            float2 v0, v1;
            v0.x = acc[mt][nt][0] + bb.x; v0.y = acc[mt][nt][1] + bb.y;
            v1.x = acc[mt][nt][2] + bb.x; v1.y = acc[mt][nt][3] + bb.y;
            *reinterpret_cast<float2*>(out + (size_t)m * VDIM + n)       = v0;
            *reinterpret_cast<float2*>(out + (size_t)(m + 8) * VDIM + n) = v1;
        }
    }
}

// ---------------- host ----------------
typedef CUresult (*PFN_encodeTiled)(CUtensorMap*, CUtensorMapDataType, cuuint32_t, void*,
                                    const cuuint64_t*, const cuuint64_t*, const cuuint32_t*,
                                    const cuuint32_t*, CUtensorMapInterleave, CUtensorMapSwizzle,
                                    CUtensorMapL2promotion, CUtensorMapFloatOOBfill);

extern "C" void kernel_launch(void* const* d_in, const int* in_sizes, int n_in,
                              void* d_out, int out_size) {
    const float* enc  = (const float*)d_in[0];   // (8,256,512)
    const float* pred = (const float*)d_in[1];   // (8,64,512)
    const float* W    = (const float*)d_in[2];   // (1024,512)
    const float* b    = (const float*)d_in[3];   // (1024,)
    float* out = (float*)d_out;                  // (8,256,64,1024) fp32

    // driver entry point for tensormap encode (no -lcuda needed)
    void* fn = nullptr;
    cudaDriverEntryPointQueryResult qr;
    cudaGetDriverEntryPoint("cuTensorMapEncodeTiled", &fn, cudaEnableDefault, &qr);
    PFN_encodeTiled encode = (PFN_encodeTiled)fn;

    void *ahPtr = nullptr, *whPtr = nullptr;
    cudaGetSymbolAddress(&ahPtr, Ah_g);
    cudaGetSymbolAddress(&whPtr, Wh_g);

    CUtensorMap tmA, tmB;
    {
        cuuint64_t dims[2] = { (cuuint64_t)CK * 2, (cuuint64_t)MTOT };   // bytes, rows
        cuuint64_t strides[1] = { (cuuint64_t)CK * 2 };
        cuuint32_t box[2] = { BK * 2, BM };                              // 128B x 128 rows
        cuuint32_t es[2] = { 1, 1 };
        encode(&tmA, CU_TENSOR_MAP_DATA_TYPE_UINT8, 2, ahPtr, dims, strides, box, es,
               CU_TENSOR_MAP_INTERLEAVE_NONE, CU_TENSOR_MAP_SWIZZLE_128B,
               CU_TENSOR_MAP_L2_PROMOTION_L2_128B, CU_TENSOR_MAP_FLOAT_OOB_FILL_NONE);
    }
    {
        cuuint64_t dims[2] = { (cuuint64_t)CK * 2, (cuuint64_t)VDIM };
        cuuint64_t strides[1] = { (cuuint64_t)CK * 2 };
        cuuint32_t box[2] = { BK * 2, BN };
        cuuint32_t es[2] = { 1, 1 };
        encode(&tmB, CU_TENSOR_MAP_DATA_TYPE_UINT8, 2, whPtr, dims, strides, box, es,
               CU_TENSOR_MAP_INTERLEAVE_NONE, CU_TENSOR_MAP_SWIZZLE_128B,
               CU_TENSOR_MAP_L2_PROMOTION_L2_128B, CU_TENSOR_MAP_FLOAT_OOB_FILL_NONE);
    }

    cudaFuncSetAttribute(joiner_gemm, cudaFuncAttributeMaxDynamicSharedMemorySize, SMEM_DYN);

    conv_w<<<VDIM * CK / 4 / 256, 256>>>(W);                   // 512 blocks
    conv_a<<<(size_t)MTOT * CK / 4 / 256, 256>>>(enc, pred);   // 65536 blocks
    dim3 grid(VDIM / BN, MTOT / BM);                           // (8, 1024)
    joiner_gemm<<<grid, NTHREADS, SMEM_DYN>>>(tmA, tmB, b, out);
}

// round 14
// speedup vs baseline: 1.0575x; 1.0032x over previous
#include <cuda_runtime.h>
#include <cuda.h>
#include <cuda_fp16.h>
#include <cstdint>

#define CK     512
#define VDIM   1024
#define MTOT   131072
#define BM     128
#define BN     128
#define BK     64
#define NCHUNK (CK / BK)       // 8
#define NTHREADS 128

#define A_BYTES     16384      // 128 rows x 128B fp16
#define STAGE_BYTES 32768      // A 16KB + B 16KB
#define MBAR_OFF    98304      // after 3 stages
#define SMEM_DYN    (98304 + 128 + 1024)   // stages + mbars + align slack

// fp16 scratch: tanh(enc+pred) precomputed once, W converted once.
__device__ __half Ah_g[(size_t)MTOT * CK];   // 128 MB
__device__ __half Wh_g[(size_t)VDIM * CK];   // 1 MB

__device__ __forceinline__ float fast_tanh(float x) {
    float y; asm("tanh.approx.f32 %0, %1;" : "=f"(y) : "f"(x)); return y;
}
__device__ __forceinline__ uint32_t smem_u32(const void* p) {
    uint32_t a;
    asm("{ .reg .u64 t; cvta.to.shared.u64 t, %1; cvt.u32.u64 %0, t; }" : "=r"(a) : "l"(p));
    return a;
}
__device__ __forceinline__ uint32_t swz(uint32_t x) { return x ^ ((x >> 3) & 0x70); }

__device__ __forceinline__ void mbar_wait(uint32_t mbar, uint32_t parity) {
    uint32_t done;
    asm volatile(
        "{\n\t.reg .pred p;\n\t"
        "mbarrier.try_wait.parity.acquire.cta.shared::cta.b64 p, [%1], %2;\n\t"
        "selp.b32 %0, 1, 0, p;\n\t}"
        : "=r"(done) : "r"(mbar), "r"(parity) : "memory");
    if (!done) {
        asm volatile(
            "{\n\t.reg .pred P1;\n\t"
            "W_%=:\n\t"
            "mbarrier.try_wait.parity.acquire.cta.shared::cta.b64 P1, [%0], %1, 0x989680;\n\t"
            "@P1 bra.uni D_%=;\n\t"
            "bra.uni W_%=;\n\t"
            "D_%=:\n\t}"
            :: "r"(mbar), "r"(parity) : "memory");
    }
}

// ---------------- prolog kernels ----------------
__global__ void __launch_bounds__(256) conv_w(const float* __restrict__ W) {
    const int i = blockIdx.x * 256 + threadIdx.x;       // 131072 float4s
    const float4 w = reinterpret_cast<const float4*>(W)[i];
    __half2* o = reinterpret_cast<__half2*>(Wh_g);
    o[2 * i]     = __floats2half2_rn(w.x, w.y);
    o[2 * i + 1] = __floats2half2_rn(w.z, w.w);
}

__global__ void __launch_bounds__(256) conv_a(const float* __restrict__ enc,
                                              const float* __restrict__ pred) {
    const int g = blockIdx.x * 256 + threadIdx.x;       // float4 id
    const int m = g >> 7;
    const int t = g & 127;
    const float4 e = reinterpret_cast<const float4*>(enc  + (size_t)(m >> 6) * CK)[t];
    const float4 p = reinterpret_cast<const float4*>(pred + (size_t)(((m >> 14) << 6) | (m & 63)) * CK)[t];
    __half2 h0 = __floats2half2_rn(fast_tanh(e.x + p.x), fast_tanh(e.y + p.y));
    __half2 h1 = __floats2half2_rn(fast_tanh(e.z + p.z), fast_tanh(e.w + p.w));
    __half2* o = reinterpret_cast<__half2*>(Ah_g);
    o[2 * (size_t)g]     = h0;
    o[2 * (size_t)g + 1] = h1;
}

// ------- main GEMM: 128x128, 4 warps (64x64), 2 CTAs/SM, TMA, frag double-buffer -------
__global__ void __launch_bounds__(NTHREADS, 2)
joiner_gemm(const __grid_constant__ CUtensorMap tmA,
            const __grid_constant__ CUtensorMap tmB,
            const float* __restrict__ bias, float* __restrict__ out)
{
    extern __shared__ char smem_raw[];
    const uint32_t smemBase = (smem_u32(smem_raw) + 1023u) & ~1023u;

    const int tid  = threadIdx.x;
    const int lane = tid & 31;
    const int wid  = tid >> 5;
    const int n0 = blockIdx.x * BN;       // x = n-tile (8) -> A L2 reuse within wave
    const int m0 = blockIdx.y * BM;       // y = m-tile (1024)
    const int warpM = (wid & 1) * 64;
    const int warpN = (wid >> 1) * 64;

    const uint32_t mbar0 = smemBase + MBAR_OFF;

    if (tid == 0) {
        #pragma unroll
        for (int s = 0; s < 3; ++s)
            asm volatile("mbarrier.init.shared.b64 [%0], 1;" :: "r"(mbar0 + s * 8) : "memory");
    }
    __syncthreads();

    float acc[4][8][4];
    #pragma unroll
    for (int mt = 0; mt < 4; ++mt)
        #pragma unroll
        for (int nt = 0; nt < 8; ++nt)
            #pragma unroll
            for (int i = 0; i < 4; ++i) acc[mt][nt][i] = 0.0f;

    // ---- TMA stage issue (thread 0) ----
    auto issue_stage = [&](int c, int s) {
        const uint32_t sa = smemBase + (uint32_t)s * STAGE_BYTES;
        const uint32_t sb = sa + A_BYTES;
        const uint32_t mb = mbar0 + (uint32_t)s * 8;
        asm volatile("mbarrier.arrive.expect_tx.shared.b64 _, [%0], %1;"
                     :: "r"(mb), "r"((uint32_t)STAGE_BYTES) : "memory");
        const int xb = c * (BK * 2);
        asm volatile(
            "cp.async.bulk.tensor.2d.shared::cta.global.tile.mbarrier::complete_tx::bytes "
            "[%0], [%1, {%2, %3}], [%4];"
            :: "r"(sa), "l"(&tmA), "r"(xb), "r"(m0), "r"(mb) : "memory");
        asm volatile(
            "cp.async.bulk.tensor.2d.shared::cta.global.tile.mbarrier::complete_tx::bytes "
            "[%0], [%1, {%2, %3}], [%4];"
            :: "r"(sb), "l"(&tmB), "r"(xb), "r"(n0), "r"(mb) : "memory");
    };

    // fragment addressing constants (identical to R12 passing kernel)
    const uint32_t kbAoff = (uint32_t)((lane >> 4) << 4);
    const int jgrp = lane >> 3;
    const uint32_t bNoff = (uint32_t)((jgrp >> 1) * 8 + (lane & 7));
    const uint32_t bKoff = (uint32_t)((jgrp & 1) * 16);

    auto compute_stage = [&](int s) {
        const uint32_t sa = smemBase + (uint32_t)s * STAGE_BYTES;
        const uint32_t sb = sa + A_BYTES;

        uint32_t a[2][4][4];   // k16-level double-buffered fragments
        uint32_t b[2][8][2];

        // EXACT R12 mapping, parameterized by destination buffer
        auto loadAB = [&](int k16, int buf) {
            const uint32_t kbA = (uint32_t)(k16 * 32) + kbAoff;
            #pragma unroll
            for (int mt = 0; mt < 4; ++mt) {
                const uint32_t ad = sa + swz((uint32_t)((warpM + mt * 16 + (lane & 15)) * 128) + kbA);
                asm volatile("ldmatrix.sync.aligned.m8n8.x4.shared.b16 {%0,%1,%2,%3}, [%4];"
                    : "=r"(a[buf][mt][0]), "=r"(a[buf][mt][1]), "=r"(a[buf][mt][2]), "=r"(a[buf][mt][3])
                    : "r"(ad));
            }
            const uint32_t kbB = (uint32_t)(k16 * 32) + bKoff;
            #pragma unroll
            for (int np = 0; np < 4; ++np) {
                const uint32_t ad = sb + swz((uint32_t)(warpN + np * 16 + bNoff) * 128u + kbB);
                asm volatile("ldmatrix.sync.aligned.m8n8.x4.shared.b16 {%0,%1,%2,%3}, [%4];"
                    : "=r"(b[buf][2 * np][0]), "=r"(b[buf][2 * np][1]),
                      "=r"(b[buf][2 * np + 1][0]), "=r"(b[buf][2 * np + 1][1])
                    : "r"(ad));
            }
        };

        loadAB(0, 0);
        #pragma unroll
        for (int k16 = 0; k16 < 4; ++k16) {
            const int cur = k16 & 1;
            if (k16 < 3) loadAB(k16 + 1, cur ^ 1);   // prefetch next frags under this k16's MMAs
            #pragma unroll
            for (int mt = 0; mt < 4; ++mt)
                #pragma unroll
                for (int nt = 0; nt < 8; ++nt)
                    asm volatile(
                        "mma.sync.aligned.m16n8k16.row.col.f32.f16.f16.f32 "
                        "{%0,%1,%2,%3},{%4,%5,%6,%7},{%8,%9},{%0,%1,%2,%3};"
                        : "+f"(acc[mt][nt][0]), "+f"(acc[mt][nt][1]),
                          "+f"(acc[mt][nt][2]), "+f"(acc[mt][nt][3])
                        : "r"(a[cur][mt][0]), "r"(a[cur][mt][1]), "r"(a[cur][mt][2]), "r"(a[cur][mt][3]),
                          "r"(b[cur][nt][0]), "r"(b[cur][nt][1]));
        }
    };

    if (tid == 0) { issue_stage(0, 0); issue_stage(1, 1); }

    #pragma unroll 1
    for (int c = 0; c < NCHUNK; ++c) {
        mbar_wait(mbar0 + (uint32_t)(c % 3) * 8, (uint32_t)((c / 3) & 1));
        compute_stage(c % 3);
        __syncthreads();
        if (tid == 0 && c + 2 < NCHUNK) issue_stage(c + 2, (c + 2) % 3);
    }

    // ---- epilogue: bias + fp32 store ----
    const int gr = lane >> 2;
    const int gc = (lane & 3) * 2;
    #pragma unroll
    for (int mt = 0; mt < 4; ++mt) {
        const int m = m0 + warpM + mt * 16 + gr;
        #pragma unroll
        for (int nt = 0; nt < 8; ++nt) {
            const int n = n0 + warpN + nt * 8 + gc;
            const float2 bb = *reinterpret_cast<const float2*>(bias + n);
            float2 v0, v1;
            v0.x = acc[mt][nt][0] + bb.x; v0.y = acc[mt][nt][1] + bb.y;
            v1.x = acc[mt][nt][2] + bb.x; v1.y = acc[mt][nt][3] + bb.y;
            *reinterpret_cast<float2*>(out + (size_t)m * VDIM + n)       = v0;
            *reinterpret_cast<float2*>(out + (size_t)(m + 8) * VDIM + n) = v1;
        }
    }
}

// ---------------- host ----------------
typedef CUresult (*PFN_encodeTiled)(CUtensorMap*, CUtensorMapDataType, cuuint32_t, void*,
                                    const cuuint64_t*, const cuuint64_t*, const cuuint32_t*,
                                    const cuuint32_t*, CUtensorMapInterleave, CUtensorMapSwizzle,
                                    CUtensorMapL2promotion, CUtensorMapFloatOOBfill);

extern "C" void kernel_launch(void* const* d_in, const int* in_sizes, int n_in,
                              void* d_out, int out_size) {
    const float* enc  = (const float*)d_in[0];   // (8,256,512)
    const float* pred = (const float*)d_in[1];   // (8,64,512)
    const float* W    = (const float*)d_in[2];   // (1024,512)
    const float* b    = (const float*)d_in[3];   // (1024,)
    float* out = (float*)d_out;                  // (8,256,64,1024) fp32

    void* fn = nullptr;
    cudaDriverEntryPointQueryResult qr;
    cudaGetDriverEntryPoint("cuTensorMapEncodeTiled", &fn, cudaEnableDefault, &qr);
    PFN_encodeTiled encode = (PFN_encodeTiled)fn;

    void *ahPtr = nullptr, *whPtr = nullptr;
    cudaGetSymbolAddress(&ahPtr, Ah_g);
    cudaGetSymbolAddress(&whPtr, Wh_g);

    CUtensorMap tmA, tmB;
    {
        cuuint64_t dims[2] = { (cuuint64_t)CK * 2, (cuuint64_t)MTOT };
        cuuint64_t strides[1] = { (cuuint64_t)CK * 2 };
        cuuint32_t box[2] = { BK * 2, BM };
        cuuint32_t es[2] = { 1, 1 };
        encode(&tmA, CU_TENSOR_MAP_DATA_TYPE_UINT8, 2, ahPtr, dims, strides, box, es,
               CU_TENSOR_MAP_INTERLEAVE_NONE, CU_TENSOR_MAP_SWIZZLE_128B,
               CU_TENSOR_MAP_L2_PROMOTION_L2_128B, CU_TENSOR_MAP_FLOAT_OOB_FILL_NONE);
    }
    {
        cuuint64_t dims[2] = { (cuuint64_t)CK * 2, (cuuint64_t)VDIM };
        cuuint64_t strides[1] = { (cuuint64_t)CK * 2 };
        cuuint32_t box[2] = { BK * 2, BN };
        cuuint32_t es[2] = { 1, 1 };
        encode(&tmB, CU_TENSOR_MAP_DATA_TYPE_UINT8, 2, whPtr, dims, strides, box, es,
               CU_TENSOR_MAP_INTERLEAVE_NONE, CU_TENSOR_MAP_SWIZZLE_128B,
               CU_TENSOR_MAP_L2_PROMOTION_L2_128B, CU_TENSOR_MAP_FLOAT_OOB_FILL_NONE);
    }

    cudaFuncSetAttribute(joiner_gemm, cudaFuncAttributeMaxDynamicSharedMemorySize, SMEM_DYN);

    conv_w<<<VDIM * CK / 4 / 256, 256>>>(W);                   // 512 blocks
    conv_a<<<(size_t)MTOT * CK / 4 / 256, 256>>>(enc, pred);   // 65536 blocks
    dim3 grid(VDIM / BN, MTOT / BM);                           // (8, 1024)
    joiner_gemm<<<grid, NTHREADS, SMEM_DYN>>>(tmA, tmB, b, out);
}

// round 15
// speedup vs baseline: 1.0673x; 1.0093x over previous
#include <cuda_runtime.h>
#include <cuda.h>
#include <cuda_fp16.h>
#include <cstdint>

#define CK     512
#define VDIM   1024
#define MTOT   131072
#define BM     128
#define BN     128
#define BK     64
#define NCHUNK (CK / BK)       // 8
#define NTHREADS 128
#define NSLOTS  296            // 2 CTAs/SM x 148 SMs
#define NTILES  8192           // (MTOT/BM) * (VDIM/BN)

#define A_BYTES     16384      // 128 rows x 128B fp16
#define STAGE_BYTES 32768      // A 16KB + B 16KB
#define MBAR_OFF    98304      // after 3 stages
#define SMEM_DYN    (98304 + 128 + 1024)

// fp16 scratch: tanh(enc+pred) precomputed once, W converted once.
__device__ __half Ah_g[(size_t)MTOT * CK];   // 128 MB
__device__ __half Wh_g[(size_t)VDIM * CK];   // 1 MB

__device__ __forceinline__ float fast_tanh(float x) {
    float y; asm("tanh.approx.f32 %0, %1;" : "=f"(y) : "f"(x)); return y;
}
__device__ __forceinline__ uint32_t smem_u32(const void* p) {
    uint32_t a;
    asm("{ .reg .u64 t; cvta.to.shared.u64 t, %1; cvt.u32.u64 %0, t; }" : "=r"(a) : "l"(p));
    return a;
}
__device__ __forceinline__ uint32_t swz(uint32_t x) { return x ^ ((x >> 3) & 0x70); }

__device__ __forceinline__ void mbar_wait(uint32_t mbar, uint32_t parity) {
    uint32_t done;
    asm volatile(
        "{\n\t.reg .pred p;\n\t"
        "mbarrier.try_wait.parity.acquire.cta.shared::cta.b64 p, [%1], %2;\n\t"
        "selp.b32 %0, 1, 0, p;\n\t}"
        : "=r"(done) : "r"(mbar), "r"(parity) : "memory");
    if (!done) {
        asm volatile(
            "{\n\t.reg .pred P1;\n\t"
            "W_%=:\n\t"
            "mbarrier.try_wait.parity.acquire.cta.shared::cta.b64 P1, [%0], %1, 0x989680;\n\t"
            "@P1 bra.uni D_%=;\n\t"
            "bra.uni W_%=;\n\t"
            "D_%=:\n\t}"
            :: "r"(mbar), "r"(parity) : "memory");
    }
}

// ---------------- prolog kernels ----------------
__global__ void __launch_bounds__(256) conv_w(const float* __restrict__ W) {
    const int i = blockIdx.x * 256 + threadIdx.x;       // 131072 float4s
    const float4 w = reinterpret_cast<const float4*>(W)[i];
    __half2* o = reinterpret_cast<__half2*>(Wh_g);
    o[2 * i]     = __floats2half2_rn(w.x, w.y);
    o[2 * i + 1] = __floats2half2_rn(w.z, w.w);
}

__global__ void __launch_bounds__(256) conv_a(const float* __restrict__ enc,
                                              const float* __restrict__ pred) {
    const int g = blockIdx.x * 256 + threadIdx.x;       // float4 id
    const int m = g >> 7;
    const int t = g & 127;
    const float4 e = reinterpret_cast<const float4*>(enc  + (size_t)(m >> 6) * CK)[t];
    const float4 p = reinterpret_cast<const float4*>(pred + (size_t)(((m >> 14) << 6) | (m & 63)) * CK)[t];
    __half2 h0 = __floats2half2_rn(fast_tanh(e.x + p.x), fast_tanh(e.y + p.y));
    __half2 h1 = __floats2half2_rn(fast_tanh(e.z + p.z), fast_tanh(e.w + p.w));
    __half2* o = reinterpret_cast<__half2*>(Ah_g);
    o[2 * (size_t)g]     = h0;
    o[2 * (size_t)g + 1] = h1;
}

// ------- persistent GEMM: 296 CTAs, 128x128 tiles, never-draining TMA pipeline -------
__global__ void __launch_bounds__(NTHREADS, 2)
joiner_gemm(const __grid_constant__ CUtensorMap tmA,
            const __grid_constant__ CUtensorMap tmB,
            const float* __restrict__ bias, float* __restrict__ out)
{
    extern __shared__ char smem_raw[];
    const uint32_t smemBase = (smem_u32(smem_raw) + 1023u) & ~1023u;

    const int tid  = threadIdx.x;
    const int lane = tid & 31;
    const int wid  = tid >> 5;
    const int slot = blockIdx.x;
    const int warpM = (wid & 1) * 64;
    const int warpN = (wid >> 1) * 64;

    const uint32_t mbar0 = smemBase + MBAR_OFF;
    if (tid == 0) {
        #pragma unroll
        for (int s = 0; s < 3; ++s)
            asm volatile("mbarrier.init.shared.b64 [%0], 1;" :: "r"(mbar0 + s * 8) : "memory");
    }
    __syncthreads();

    const int nTiles = (NTILES - slot + NSLOTS - 1) / NSLOTS;
    const int nQ = nTiles * NCHUNK;

    // ---- TMA issue for global chunk q (thread 0) ----
    auto issue_q = [&](int q) {
        const int t  = slot + (q >> 3) * NSLOTS;
        const int c  = q & 7;
        const int m0q = (t >> 3) * BM;
        const int n0q = (t & 7) * BN;
        const uint32_t s = (uint32_t)(q % 3);
        const uint32_t sa = smemBase + s * STAGE_BYTES;
        const uint32_t sb = sa + A_BYTES;
        const uint32_t mb = mbar0 + s * 8;
        asm volatile("mbarrier.arrive.expect_tx.shared.b64 _, [%0], %1;"
                     :: "r"(mb), "r"((uint32_t)STAGE_BYTES) : "memory");
        const int xb = c * (BK * 2);
        asm volatile(
            "cp.async.bulk.tensor.2d.shared::cta.global.tile.mbarrier::complete_tx::bytes "
            "[%0], [%1, {%2, %3}], [%4];"
            :: "r"(sa), "l"(&tmA), "r"(xb), "r"(m0q), "r"(mb) : "memory");
        asm volatile(
            "cp.async.bulk.tensor.2d.shared::cta.global.tile.mbarrier::complete_tx::bytes "
            "[%0], [%1, {%2, %3}], [%4];"
            :: "r"(sb), "l"(&tmB), "r"(xb), "r"(n0q), "r"(mb) : "memory");
    };

    // fragment addressing constants (identical to R14 passing kernel)
    const uint32_t kbAoff = (uint32_t)((lane >> 4) << 4);
    const int jgrp = lane >> 3;
    const uint32_t bNoff = (uint32_t)((jgrp >> 1) * 8 + (lane & 7));
    const uint32_t bKoff = (uint32_t)((jgrp & 1) * 16);

    float acc[4][8][4];
    #pragma unroll
    for (int mt = 0; mt < 4; ++mt)
        #pragma unroll
        for (int nt = 0; nt < 8; ++nt)
            #pragma unroll
            for (int i = 0; i < 4; ++i) acc[mt][nt][i] = 0.0f;

    auto compute_stage = [&](int s) {
        const uint32_t sa = smemBase + (uint32_t)s * STAGE_BYTES;
        const uint32_t sb = sa + A_BYTES;

        uint32_t a[2][4][4];
        uint32_t b[2][8][2];
        auto loadAB = [&](int k16, int buf) {
            const uint32_t kbA = (uint32_t)(k16 * 32) + kbAoff;
            #pragma unroll
            for (int mt = 0; mt < 4; ++mt) {
                const uint32_t ad = sa + swz((uint32_t)((warpM + mt * 16 + (lane & 15)) * 128) + kbA);
                asm volatile("ldmatrix.sync.aligned.m8n8.x4.shared.b16 {%0,%1,%2,%3}, [%4];"
                    : "=r"(a[buf][mt][0]), "=r"(a[buf][mt][1]), "=r"(a[buf][mt][2]), "=r"(a[buf][mt][3])
                    : "r"(ad));
            }
            const uint32_t kbB = (uint32_t)(k16 * 32) + bKoff;
            #pragma unroll
            for (int np = 0; np < 4; ++np) {
                const uint32_t ad = sb + swz((uint32_t)(warpN + np * 16 + bNoff) * 128u + kbB);
                asm volatile("ldmatrix.sync.aligned.m8n8.x4.shared.b16 {%0,%1,%2,%3}, [%4];"
                    : "=r"(b[buf][2 * np][0]), "=r"(b[buf][2 * np][1]),
                      "=r"(b[buf][2 * np + 1][0]), "=r"(b[buf][2 * np + 1][1])
                    : "r"(ad));
            }
        };

        loadAB(0, 0);
        #pragma unroll
        for (int k16 = 0; k16 < 4; ++k16) {
            const int cur = k16 & 1;
            if (k16 < 3) loadAB(k16 + 1, cur ^ 1);
            #pragma unroll
            for (int mt = 0; mt < 4; ++mt)
                #pragma unroll
                for (int nt = 0; nt < 8; ++nt)
                    asm volatile(
                        "mma.sync.aligned.m16n8k16.row.col.f32.f16.f16.f32 "
                        "{%0,%1,%2,%3},{%4,%5,%6,%7},{%8,%9},{%0,%1,%2,%3};"
                        : "+f"(acc[mt][nt][0]), "+f"(acc[mt][nt][1]),
                          "+f"(acc[mt][nt][2]), "+f"(acc[mt][nt][3])
                        : "r"(a[cur][mt][0]), "r"(a[cur][mt][1]), "r"(a[cur][mt][2]), "r"(a[cur][mt][3]),
                          "r"(b[cur][nt][0]), "r"(b[cur][nt][1]));
        }
    };

    if (tid == 0) { issue_q(0); issue_q(1); }

    const int gr = lane >> 2;
    const int gc = (lane & 3) * 2;

    #pragma unroll 1
    for (int q = 0; q < nQ; ++q) {
        mbar_wait(mbar0 + (uint32_t)(q % 3) * 8, (uint32_t)((q / 3) & 1));
        compute_stage(q % 3);
        __syncthreads();                         // stage reads complete before reuse
        if (tid == 0 && q + 2 < nQ) issue_q(q + 2);   // next tiles' chunks overlap epilogue

        if ((q & 7) == 7) {
            // ---- epilogue for tile (q>>3): bias + fp32 store, then reset acc ----
            const int t  = slot + (q >> 3) * NSLOTS;
            const int m0 = (t >> 3) * BM;
            const int n0 = (t & 7) * BN;
            #pragma unroll
            for (int mt = 0; mt < 4; ++mt) {
                const int m = m0 + warpM + mt * 16 + gr;
                #pragma unroll
                for (int nt = 0; nt < 8; ++nt) {
                    const int n = n0 + warpN + nt * 8 + gc;
                    const float2 bb = *reinterpret_cast<const float2*>(bias + n);
                    float2 v0, v1;
                    v0.x = acc[mt][nt][0] + bb.x; v0.y = acc[mt][nt][1] + bb.y;
                    v1.x = acc[mt][nt][2] + bb.x; v1.y = acc[mt][nt][3] + bb.y;
                    *reinterpret_cast<float2*>(out + (size_t)m * VDIM + n)       = v0;
                    *reinterpret_cast<float2*>(out + (size_t)(m + 8) * VDIM + n) = v1;
                }
            }
            #pragma unroll
            for (int mt = 0; mt < 4; ++mt)
                #pragma unroll
                for (int nt = 0; nt < 8; ++nt)
                    #pragma unroll
                    for (int i = 0; i < 4; ++i) acc[mt][nt][i] = 0.0f;
        }
    }
}

// ---------------- host ----------------
typedef CUresult (*PFN_encodeTiled)(CUtensorMap*, CUtensorMapDataType, cuuint32_t, void*,
                                    const cuuint64_t*, const cuuint64_t*, const cuuint32_t*,
                                    const cuuint32_t*, CUtensorMapInterleave, CUtensorMapSwizzle,
                                    CUtensorMapL2promotion, CUtensorMapFloatOOBfill);

extern "C" void kernel_launch(void* const* d_in, const int* in_sizes, int n_in,
                              void* d_out, int out_size) {
    const float* enc  = (const float*)d_in[0];   // (8,256,512)
    const float* pred = (const float*)d_in[1];   // (8,64,512)
    const float* W    = (const float*)d_in[2];   // (1024,512)
    const float* b    = (const float*)d_in[3];   // (1024,)
    float* out = (float*)d_out;                  // (8,256,64,1024) fp32

    void* fn = nullptr;
    cudaDriverEntryPointQueryResult qr;
    cudaGetDriverEntryPoint("cuTensorMapEncodeTiled", &fn, cudaEnableDefault, &qr);
    PFN_encodeTiled encode = (PFN_encodeTiled)fn;

    void *ahPtr = nullptr, *whPtr = nullptr;
    cudaGetSymbolAddress(&ahPtr, Ah_g);
    cudaGetSymbolAddress(&whPtr, Wh_g);

    CUtensorMap tmA, tmB;
    {
        cuuint64_t dims[2] = { (cuuint64_t)CK * 2, (cuuint64_t)MTOT };
        cuuint64_t strides[1] = { (cuuint64_t)CK * 2 };
        cuuint32_t box[2] = { BK * 2, BM };
        cuuint32_t es[2] = { 1, 1 };
        encode(&tmA, CU_TENSOR_MAP_DATA_TYPE_UINT8, 2, ahPtr, dims, strides, box, es,
               CU_TENSOR_MAP_INTERLEAVE_NONE, CU_TENSOR_MAP_SWIZZLE_128B,
               CU_TENSOR_MAP_L2_PROMOTION_L2_128B, CU_TENSOR_MAP_FLOAT_OOB_FILL_NONE);
    }
    {
        cuuint64_t dims[2] = { (cuuint64_t)CK * 2, (cuuint64_t)VDIM };
        cuuint64_t strides[1] = { (cuuint64_t)CK * 2 };
        cuuint32_t box[2] = { BK * 2, BN };
        cuuint32_t es[2] = { 1, 1 };
        encode(&tmB, CU_TENSOR_MAP_DATA_TYPE_UINT8, 2, whPtr, dims, strides, box, es,
               CU_TENSOR_MAP_INTERLEAVE_NONE, CU_TENSOR_MAP_SWIZZLE_128B,
               CU_TENSOR_MAP_L2_PROMOTION_L2_128B, CU_TENSOR_MAP_FLOAT_OOB_FILL_NONE);
    }

    cudaFuncSetAttribute(joiner_gemm, cudaFuncAttributeMaxDynamicSharedMemorySize, SMEM_DYN);

    conv_w<<<VDIM * CK / 4 / 256, 256>>>(W);                   // 512 blocks
    conv_a<<<(size_t)MTOT * CK / 4 / 256, 256>>>(enc, pred);   // 65536 blocks
    joiner_gemm<<<NSLOTS, NTHREADS, SMEM_DYN>>>(tmA, tmB, b, out);
}